// round 16
// baseline (speedup 1.0000x reference)
#include <cuda_runtime.h>
#include <cuda_bf16.h>
#include <math.h>
#include <stdint.h>

#define TT 512
#define BB 32
#define HH 512
#define NROWS 16384
#define LDK 544            // 514 padded to 34*16
#define NG 4096

// SMEM layout (bytes)
#define WP       1104      // row pitch for Wsm / Xs (1088 data + 16 pad)
#define WS_OFF   0         // W_ih slice: 128 rows x WP        = 141312
#define XS_OFF   141312    // x tile, DOUBLE buffered: 2 x 17664
#define XS_SZ    17664
#define AB_OFF   176640    // h tile, DOUBLE buffered: 2 x 16640
#define AB_SZ    16640
#define HL_OFF   209920    // hloc staging: 1KB
#define GS_OFF   210944    // gsm: 128 x 17 f32 = 8704
#define LSTM_SMEM 219648

__device__ __nv_bfloat16 g_xb[(size_t)NROWS * LDK];
__device__ __nv_bfloat16 g_wb[(size_t)NG * LDK];
__device__ float         g_bias[NG];
// h layout: [dir][t][bh(2)][g(16)][b(16)][32]
__device__ __nv_bfloat16 g_hs[(size_t)2 * TT * 2 * 8192];
__device__ float         g_em[(size_t)NROWS * 6];

static __device__ __forceinline__ unsigned packbf(float lo, float hi) {
    __nv_bfloat162 v = __floats2bfloat162_rn(lo, hi);
    return *reinterpret_cast<unsigned*>(&v);
}

static __device__ __forceinline__ void mma_bf16(float& c0, float& c1, float& c2, float& c3,
                                                unsigned a0, unsigned a1, unsigned a2, unsigned a3,
                                                unsigned b0, unsigned b1) {
    asm volatile(
        "mma.sync.aligned.m16n8k16.row.col.f32.bf16.bf16.f32 "
        "{%0,%1,%2,%3},{%4,%5,%6,%7},{%8,%9},{%0,%1,%2,%3};"
        : "+f"(c0), "+f"(c1), "+f"(c2), "+f"(c3)
        : "r"(a0), "r"(a1), "r"(a2), "r"(a3), "r"(b0), "r"(b1));
}

static __device__ __forceinline__ float fsig(float x) {
    return __frcp_rn(1.f + __expf(-x));
}
static __device__ __forceinline__ float ftanh(float x) {
    float t = __expf(2.f * x);
    return (t - 1.f) * __frcp_rn(t + 1.f);
}

// ---- K1: x = [emb[ids] | eeg[:,:,4:6] | pad] -> bf16 [t*32+b][544] ---------
__global__ void build_x_k(const int* __restrict__ ids, const float* __restrict__ eeg,
                          const float* __restrict__ emb) {
    int row = blockIdx.x, t = row >> 5, b = row & 31;
    int id = ids[b * TT + t];
    const float* er = emb + (size_t)id * 512;
    __nv_bfloat16* xr = g_xb + (size_t)row * LDK;
    for (int d = threadIdx.x; d < LDK; d += blockDim.x) {
        float v;
        if (d < 512)      v = er[d];
        else if (d < 514) v = eeg[((size_t)(b * TT + t)) * 8 + 4 + (d - 512)];
        else              v = 0.f;
        xr[d] = __float2bfloat16(v);
    }
}

// ---- K1b: pack W_ih both dirs -> bf16 [4096][544], bias f32 ----------------
__global__ void pack_w_k(const float* __restrict__ wf, const float* __restrict__ wb,
                         const float* __restrict__ bf, const float* __restrict__ bbv) {
    int r = blockIdx.x;
    const float* src = (r < 2048) ? (wf + (size_t)r * 514) : (wb + (size_t)(r - 2048) * 514);
    __nv_bfloat16* dst = g_wb + (size_t)r * LDK;
    for (int d = threadIdx.x; d < LDK; d += blockDim.x)
        dst[d] = __float2bfloat16((d < 514) ? src[d] : 0.f);
    if (threadIdx.x == 0) g_bias[r] = (r < 2048) ? bf[r] : bbv[r - 2048];
}

// ---- K2: fused persistent BiLSTM, DSMEM h-exchange, cluster barrier --------
// R14 structure (best passing) + double-buffered Xs with early prefetch.
__global__ void __launch_bounds__(256, 1) lstm_fused_k(const float* __restrict__ whhf,
                                                       const float* __restrict__ whhb) {
    extern __shared__ char sm[];
    unsigned smb;
    asm("{ .reg .u64 t; cvta.to.shared.u64 t, %1; cvt.u32.u64 %0, t; }"
        : "=r"(smb) : "l"(sm));
    float* gsm = (float*)(sm + GS_OFF);
    const int tid = threadIdx.x, cta = blockIdx.x;
    const int grp = cta >> 4, g = cta & 15;       // g == cluster rank
    const int dir = grp >> 1, bh = grp & 1;
    const int w = tid >> 5, l = tid & 31;

    // ---- load W_ih slice into SMEM ----
    for (int i = tid; i < 8704; i += 256) {
        int row = i / 68, col = i % 68;
        int grow = dir * 2048 + (row >> 5) * 512 + g * 32 + (row & 31);
        *(uint4*)(sm + WS_OFF + row * WP + col * 16) =
            *(const uint4*)((const char*)g_wb + (size_t)grow * (LDK * 2) + col * 16);
    }
    // ---- W_hh fragments in registers ----
    const float* W = dir ? whhb : whhf;
    unsigned Bf[32][2][2];
#pragma unroll
    for (int nf = 0; nf < 2; nf++) {
        int rloc = w * 16 + nf * 8 + (l >> 2);
        int gate = rloc >> 5, jloc = rloc & 31;
        const float* Wr = W + (size_t)(gate * 512 + g * 32 + jloc) * 512;
#pragma unroll
        for (int ks = 0; ks < 32; ks++) {
            const float* p = Wr + ks * 16 + ((l & 3) << 1);
            Bf[ks][nf][0] = packbf(p[0], p[1]);
            Bf[ks][nf][1] = packbf(p[8], p[9]);
        }
    }
    const int dim = tid & 31, brow = tid >> 5;
    float bias_r[4];
#pragma unroll
    for (int G = 0; G < 4; G++)
        bias_r[G] = g_bias[dir * 2048 + G * 512 + g * 32 + dim];
    float cs0 = 0.f, cs1 = 0.f;

    const unsigned lmA  = (unsigned)((l & 15) * WP + (l >> 4) * 16);
    const unsigned lmB  = (unsigned)(((l & 7) + ((l >> 4) << 3)) * WP + ((l >> 3) & 1) * 16);
    const unsigned lmAb = (unsigned)((l & 15) * 1040 + (l >> 4) * 16);
    const unsigned ws_w = smb + WS_OFF + (unsigned)(w * 16) * WP;

    // prefetch x tile for step 0 into buf 0
    {
        const int t0 = dir ? (TT - 1) : 0;
        for (int i = tid; i < 1088; i += 256) {
            int row = i / 68, col = i % 68;
            unsigned dst = smb + XS_OFF + row * WP + col * 16;
            const char* src = (const char*)g_xb
                + ((size_t)(t0 * 32 + bh * 16 + row)) * (LDK * 2) + col * 16;
            asm volatile("cp.async.cg.shared.global [%0],[%1],16;" :: "r"(dst), "l"(src));
        }
        asm volatile("cp.async.commit_group;");
    }

    for (int step = 0; step < TT; step++) {
        const int t = dir ? (TT - 1 - step) : step;
        asm volatile("cp.async.wait_group 0;");
        __syncthreads();   // Xs buf[step&1] ready; prior hloc/Ab reads done

        // early prefetch of next x tile into the other buffer (full step ahead)
        if (step + 1 < TT) {
            const int tn = dir ? (TT - 2 - step) : (step + 1);
            unsigned xdst = smb + XS_OFF + (unsigned)(((step + 1) & 1) * XS_SZ);
            for (int i = tid; i < 1088; i += 256) {
                int row = i / 68, col = i % 68;
                const char* src = (const char*)g_xb
                    + ((size_t)(tn * 32 + bh * 16 + row)) * (LDK * 2) + col * 16;
                asm volatile("cp.async.cg.shared.global [%0],[%1],16;"
                             :: "r"(xdst + row * WP + col * 16), "l"(src));
            }
            asm volatile("cp.async.commit_group;");
        }

        float acc[2][4] = {{0.f,0.f,0.f,0.f},{0.f,0.f,0.f,0.f}};
        // ---- x projection from Xs buf[step&1] ----
        {
            const unsigned xsb = smb + XS_OFF + (unsigned)((step & 1) * XS_SZ);
#pragma unroll 4
            for (int ks = 0; ks < 34; ks++) {
                unsigned a0, a1, a2, a3, b0, b1, b2, b3;
                asm volatile("ldmatrix.sync.aligned.m8n8.x4.shared.b16 {%0,%1,%2,%3},[%4];"
                             : "=r"(a0), "=r"(a1), "=r"(a2), "=r"(a3)
                             : "r"(xsb + (unsigned)(ks * 32) + lmA));
                asm volatile("ldmatrix.sync.aligned.m8n8.x4.shared.b16 {%0,%1,%2,%3},[%4];"
                             : "=r"(b0), "=r"(b1), "=r"(b2), "=r"(b3)
                             : "r"(ws_w + (unsigned)(ks * 32) + lmB));
                mma_bf16(acc[0][0], acc[0][1], acc[0][2], acc[0][3], a0, a1, a2, a3, b0, b1);
                mma_bf16(acc[1][0], acc[1][1], acc[1][2], acc[1][3], a0, a1, a2, a3, b2, b3);
            }
        }
        // ---- recurrent part: h of previous step already in Ab ----
        if (step > 0) {
            asm volatile("barrier.cluster.wait.aligned;" ::: "memory");  // acquire
            const unsigned abb = smb + AB_OFF + (unsigned)(((step - 1) & 1) * AB_SZ);
#pragma unroll
            for (int ks = 0; ks < 32; ks++) {
                unsigned a0, a1, a2, a3;
                asm volatile("ldmatrix.sync.aligned.m8n8.x4.shared.b16 {%0,%1,%2,%3},[%4];"
                             : "=r"(a0), "=r"(a1), "=r"(a2), "=r"(a3)
                             : "r"(abb + (unsigned)(ks * 32) + lmAb));
#pragma unroll
                for (int nf = 0; nf < 2; nf++)
                    mma_bf16(acc[nf][0], acc[nf][1], acc[nf][2], acc[nf][3],
                             a0, a1, a2, a3, Bf[ks][nf][0], Bf[ks][nf][1]);
            }
        }
        // ---- scatter C: gsm[n=gate-row][m=batch] ----
        {
            const int m0 = l >> 2;
#pragma unroll
            for (int nf = 0; nf < 2; nf++) {
                int n0 = w * 16 + nf * 8 + ((l & 3) << 1);
                gsm[(n0    ) * 17 + m0    ] = acc[nf][0];
                gsm[(n0 + 1) * 17 + m0    ] = acc[nf][1];
                gsm[(n0    ) * 17 + m0 + 8] = acc[nf][2];
                gsm[(n0 + 1) * 17 + m0 + 8] = acc[nf][3];
            }
        }
        __syncthreads();
        // ---- gates + c/h update; h -> hloc staging ----
        __nv_bfloat16* hloc = (__nv_bfloat16*)(sm + HL_OFF);
#pragma unroll
        for (int pi = 0; pi < 2; pi++) {
            int m = brow + pi * 8;
            float gi = gsm[(dim     ) * 17 + m] + bias_r[0];
            float gf = gsm[(32 + dim) * 17 + m] + bias_r[1];
            float gg = gsm[(64 + dim) * 17 + m] + bias_r[2];
            float go = gsm[(96 + dim) * 17 + m] + bias_r[3];
            float si = fsig(gi), sf = fsig(gf), so = fsig(go);
            float& cs = pi ? cs1 : cs0;
            cs = sf * cs + si * ftanh(gg);
            float h = so * ftanh(cs);
            hloc[m * 32 + dim] = __float2bfloat16(h);
        }
        __syncthreads();   // hloc complete (and gsm reads done)
        // ---- DSMEM broadcast: hloc (1KB) -> all 16 peers' Ab buf[step&1] ---
        if (step + 1 < TT) {
            const unsigned bufo = (unsigned)(AB_OFF + (step & 1) * AB_SZ);
            for (int i = tid; i < 1024; i += 256) {
                int peer = i >> 6, idx = i & 63;
                int row = idx >> 2, q = idx & 3;
                uint4 v = *(const uint4*)(sm + HL_OFF + idx * 16);
                unsigned laddr = smb + bufo + (unsigned)(row * 1040 + g * 64 + q * 16);
                asm volatile(
                    "{\n\t.reg .b32 r;\n\t"
                    "mapa.shared::cluster.u32 r, %0, %1;\n\t"
                    "st.shared::cluster.v4.b32 [r], {%2,%3,%4,%5};\n\t}"
                    :: "r"(laddr), "r"(peer), "r"(v.x), "r"(v.y), "r"(v.z), "r"(v.w)
                    : "memory");
            }
        }
        // global copy for ln_emit (off the critical path; every step)
        if (tid < 64) {
            int row = tid >> 2, q = tid & 3;
            uint4 v = *(const uint4*)(sm + HL_OFF + tid * 16);
            *(uint4*)((char*)g_hs
                + ((((size_t)dir * TT + t) * 2 + bh) * 8192 + g * 512 + row * 32) * 2
                + q * 16) = v;
        }
        if (step + 1 < TT)
            asm volatile("barrier.cluster.arrive.aligned;" ::: "memory");  // release
    }
}

// ---- K4: LayerNorm(1024) + ReLU + emission; h layout [dir][t][bh][g][b][32]
__global__ void __launch_bounds__(256) ln_emit_k(const float* __restrict__ lng,
                                                 const float* __restrict__ lnb,
                                                 const float* __restrict__ wout,
                                                 const float* __restrict__ bout) {
    __shared__ float sh[1024];
    __shared__ float rs[8], rs2[8];
    __shared__ float s_mu, s_rstd;
    const int row = blockIdx.x, tid = threadIdx.x;
    const int lane = tid & 31, w = tid >> 5;
    const int t = row >> 5, b = row & 31;
    const int bh = b >> 4, bl = b & 15;
    const __nv_bfloat16* hf = g_hs + ((size_t)t * 2 + bh) * 8192 + bl * 32;
    const __nv_bfloat16* hb = hf + (size_t)TT * 2 * 8192;
    float s = 0.f, s2 = 0.f;
#pragma unroll
    for (int i = 0; i < 4; i++) {
        int idx = tid + i * 256;
        int d = idx & 511;
        int gg = d >> 5, dm = d & 31;
        float x = (idx < 512) ? __bfloat162float(hf[gg * 512 + dm])
                              : __bfloat162float(hb[gg * 512 + dm]);
        sh[idx] = x; s += x; s2 += x * x;
    }
    for (int o = 16; o; o >>= 1) {
        s  += __shfl_down_sync(0xffffffffu, s, o);
        s2 += __shfl_down_sync(0xffffffffu, s2, o);
    }
    if (!lane) { rs[w] = s; rs2[w] = s2; }
    __syncthreads();
    if (!tid) {
        float S = 0.f, S2 = 0.f;
        for (int i = 0; i < 8; i++) { S += rs[i]; S2 += rs2[i]; }
        float mu = S * (1.f / 1024.f);
        s_mu = mu;
        s_rstd = rsqrtf(S2 * (1.f / 1024.f) - mu * mu + 1e-5f);
    }
    __syncthreads();
    float mu = s_mu, rstd = s_rstd;
#pragma unroll
    for (int i = 0; i < 4; i++) {
        int idx = tid + i * 256;
        float x = (sh[idx] - mu) * rstd * lng[idx] + lnb[idx];
        sh[idx] = fmaxf(x, 0.f);
    }
    __syncthreads();
    if (w < 6) {
        float acc = 0.f;
        for (int i = lane; i < 1024; i += 32) acc = fmaf(sh[i], wout[w * 1024 + i], acc);
        for (int o = 16; o; o >>= 1) acc += __shfl_down_sync(0xffffffffu, acc, o);
        if (!lane) g_em[(size_t)row * 6 + w] = acc + bout[w];
    }
}

// ---- K5: CRF. mask is int32. -----------------------------------------------
__global__ void crf_k(const int* __restrict__ tags, const int* __restrict__ mask,
                      const float* __restrict__ st, const float* __restrict__ en,
                      const float* __restrict__ tr, float* __restrict__ out) {
    __shared__ float ll[32];
    const unsigned full = 0xffffffffu;
    const int b = threadIdx.x >> 5, j = threadIdx.x & 31;
    const bool act = j < 6;
    float trc[6];
#pragma unroll
    for (int i = 0; i < 6; i++) trc[i] = tr[i * 6 + (act ? j : 0)];
    float alpha = act ? (st[j] + g_em[b * 6 + j]) : -1e30f;
    int prev = tags[b * TT];
    float score = st[prev] + g_em[b * 6 + prev];
    int cnt = (mask[b * TT] != 0) ? 1 : 0;
    for (int t = 1; t < TT; t++) {
        float m = (mask[b * TT + t] != 0) ? 1.f : 0.f;
        cnt += (int)m;
        int tg = tags[b * TT + t];
        const float* emt = g_em + ((size_t)t * BB + b) * 6;
        score += m * (tr[prev * 6 + tg] + emt[tg]);
        prev = tg;
        float av[6];
#pragma unroll
        for (int i = 0; i < 6; i++) av[i] = __shfl_sync(full, alpha, i);
        if (act) {
            float mx = -1e30f;
#pragma unroll
            for (int i = 0; i < 6; i++) mx = fmaxf(mx, av[i] + trc[i]);
            float sm = 0.f;
#pragma unroll
            for (int i = 0; i < 6; i++) sm += __expf(av[i] + trc[i] - mx);
            float nxt = mx + __logf(sm) + emt[j];
            if (m > 0.f) alpha = nxt;
        }
    }
    int ltag = tags[b * TT + (cnt - 1)];
    float num = score + en[ltag];
    float v = act ? (alpha + en[j]) : -1e30f;
    float mx = v;
    for (int o = 16; o; o >>= 1) mx = fmaxf(mx, __shfl_xor_sync(full, mx, o));
    float sm = act ? __expf(v - mx) : 0.f;
    for (int o = 16; o; o >>= 1) sm += __shfl_xor_sync(full, sm, o);
    float den = mx + __logf(sm);
    if (j == 0) ll[b] = num - den;
    __syncthreads();
    if (threadIdx.x == 0) {
        float s = 0.f;
        for (int i = 0; i < 32; i++) s += ll[i];
        *out = -s * (1.f / 32.f);
    }
}

extern "C" void kernel_launch(void* const* d_in, const int* in_sizes, int n_in,
                              void* d_out, int out_size) {
    const int*   ids  = (const int*)  d_in[0];
    const float* eeg  = (const float*)d_in[1];
    const int*   tags = (const int*)  d_in[2];
    const int*   mask = (const int*)  d_in[3];
    const float* emb  = (const float*)d_in[4];
    const float* wihf = (const float*)d_in[5];
    const float* whhf = (const float*)d_in[6];
    const float* bf   = (const float*)d_in[7];
    const float* wihb = (const float*)d_in[8];
    const float* whhb = (const float*)d_in[9];
    const float* bb   = (const float*)d_in[10];
    const float* lng  = (const float*)d_in[11];
    const float* lnb  = (const float*)d_in[12];
    const float* wout = (const float*)d_in[13];
    const float* bout = (const float*)d_in[14];
    const float* st   = (const float*)d_in[15];
    const float* en   = (const float*)d_in[16];
    const float* tr   = (const float*)d_in[17];
    float* out = (float*)d_out;

    cudaFuncSetAttribute(lstm_fused_k, cudaFuncAttributeMaxDynamicSharedMemorySize, LSTM_SMEM);
    cudaFuncSetAttribute(lstm_fused_k, cudaFuncAttributeNonPortableClusterSizeAllowed, 1);

    build_x_k<<<NROWS, 128>>>(ids, eeg, emb);
    pack_w_k<<<NG, 128>>>(wihf, wihb, bf, bb);

    cudaLaunchConfig_t cfg = {};
    cfg.gridDim = dim3(64, 1, 1);
    cfg.blockDim = dim3(256, 1, 1);
    cfg.dynamicSmemBytes = LSTM_SMEM;
    cfg.stream = 0;
    cudaLaunchAttribute attrs[1];
    attrs[0].id = cudaLaunchAttributeClusterDimension;
    attrs[0].val.clusterDim.x = 16;
    attrs[0].val.clusterDim.y = 1;
    attrs[0].val.clusterDim.z = 1;
    cfg.attrs = attrs;
    cfg.numAttrs = 1;
    cudaLaunchKernelEx(&cfg, lstm_fused_k, whhf, whhb);

    ln_emit_k<<<NROWS, 256>>>(lng, lnb, wout, bout);
    crf_k<<<1, 1024>>>(tags, mask, st, en, tr, out);
}

// round 17
// speedup vs baseline: 1.4461x; 1.4461x over previous
#include <cuda_runtime.h>
#include <cuda_bf16.h>
#include <math.h>
#include <stdint.h>

#define TT 512
#define BB 32
#define HH 512
#define NROWS 16384
#define LDK 544            // 514 padded to 34*16
#define NG 4096

// SMEM layout (bytes)
#define WP      1104       // row pitch for Wsm / Xs (1088 data + 16 pad)
#define WS_OFF  0          // W_ih slice: 128 rows x WP       = 141312
#define XS_OFF  141312     // x tile:      16 rows x WP       =  17664
#define AB_OFF  158976     // h tile, DOUBLE buffered: 2 x 16640
#define HL_OFF  192256     // hloc staging: 1KB
#define GS_OFF  193280     // gsm: 128 x 17 f32               =  8704
#define LSTM_SMEM 201984

__device__ __nv_bfloat16 g_xb[(size_t)NROWS * LDK];
__device__ __nv_bfloat16 g_wb[(size_t)NG * LDK];
__device__ float         g_bias[NG];
// h layout: [dir][t][bh(2)][g(16)][b(16)][32]
__device__ __nv_bfloat16 g_hs[(size_t)2 * TT * 2 * 8192];
__device__ float         g_em[(size_t)NROWS * 6];

static __device__ __forceinline__ unsigned packbf(float lo, float hi) {
    __nv_bfloat162 v = __floats2bfloat162_rn(lo, hi);
    return *reinterpret_cast<unsigned*>(&v);
}

static __device__ __forceinline__ void mma_bf16(float& c0, float& c1, float& c2, float& c3,
                                                unsigned a0, unsigned a1, unsigned a2, unsigned a3,
                                                unsigned b0, unsigned b1) {
    asm volatile(
        "mma.sync.aligned.m16n8k16.row.col.f32.bf16.bf16.f32 "
        "{%0,%1,%2,%3},{%4,%5,%6,%7},{%8,%9},{%0,%1,%2,%3};"
        : "+f"(c0), "+f"(c1), "+f"(c2), "+f"(c3)
        : "r"(a0), "r"(a1), "r"(a2), "r"(a3), "r"(b0), "r"(b1));
}

static __device__ __forceinline__ float fsig(float x) {
    return __frcp_rn(1.f + __expf(-x));
}
static __device__ __forceinline__ float ftanh(float x) {
    float t = __expf(2.f * x);
    return (t - 1.f) * __frcp_rn(t + 1.f);
}

// ---- K1: x = [emb[ids] | eeg[:,:,4:6] | pad] -> bf16 [t*32+b][544] ---------
__global__ void build_x_k(const int* __restrict__ ids, const float* __restrict__ eeg,
                          const float* __restrict__ emb) {
    int row = blockIdx.x, t = row >> 5, b = row & 31;
    int id = ids[b * TT + t];
    const float* er = emb + (size_t)id * 512;
    __nv_bfloat16* xr = g_xb + (size_t)row * LDK;
    for (int d = threadIdx.x; d < LDK; d += blockDim.x) {
        float v;
        if (d < 512)      v = er[d];
        else if (d < 514) v = eeg[((size_t)(b * TT + t)) * 8 + 4 + (d - 512)];
        else              v = 0.f;
        xr[d] = __float2bfloat16(v);
    }
}

// ---- K1b: pack W_ih both dirs -> bf16 [4096][544], bias f32 ----------------
__global__ void pack_w_k(const float* __restrict__ wf, const float* __restrict__ wb,
                         const float* __restrict__ bf, const float* __restrict__ bbv) {
    int r = blockIdx.x;
    const float* src = (r < 2048) ? (wf + (size_t)r * 514) : (wb + (size_t)(r - 2048) * 514);
    __nv_bfloat16* dst = g_wb + (size_t)r * LDK;
    for (int d = threadIdx.x; d < LDK; d += blockDim.x)
        dst[d] = __float2bfloat16((d < 514) ? src[d] : 0.f);
    if (threadIdx.x == 0) g_bias[r] = (r < 2048) ? bf[r] : bbv[r - 2048];
}

// ---- K2: fused persistent BiLSTM, DSMEM h-exchange, cluster barrier --------
// R14 structure (best passing). Only change: global h copy moved AFTER the
// cluster arrive (off the release path); x prefetch issued right after arrive.
__global__ void __launch_bounds__(256, 1) lstm_fused_k(const float* __restrict__ whhf,
                                                       const float* __restrict__ whhb) {
    extern __shared__ char sm[];
    unsigned smb;
    asm("{ .reg .u64 t; cvta.to.shared.u64 t, %1; cvt.u32.u64 %0, t; }"
        : "=r"(smb) : "l"(sm));
    float* gsm = (float*)(sm + GS_OFF);
    const int tid = threadIdx.x, cta = blockIdx.x;
    const int grp = cta >> 4, g = cta & 15;       // g == cluster rank
    const int dir = grp >> 1, bh = grp & 1;
    const int w = tid >> 5, l = tid & 31;

    // ---- load W_ih slice into SMEM ----
    for (int i = tid; i < 8704; i += 256) {
        int row = i / 68, col = i % 68;
        int grow = dir * 2048 + (row >> 5) * 512 + g * 32 + (row & 31);
        *(uint4*)(sm + WS_OFF + row * WP + col * 16) =
            *(const uint4*)((const char*)g_wb + (size_t)grow * (LDK * 2) + col * 16);
    }
    // ---- W_hh fragments in registers ----
    const float* W = dir ? whhb : whhf;
    unsigned Bf[32][2][2];
#pragma unroll
    for (int nf = 0; nf < 2; nf++) {
        int rloc = w * 16 + nf * 8 + (l >> 2);
        int gate = rloc >> 5, jloc = rloc & 31;
        const float* Wr = W + (size_t)(gate * 512 + g * 32 + jloc) * 512;
#pragma unroll
        for (int ks = 0; ks < 32; ks++) {
            const float* p = Wr + ks * 16 + ((l & 3) << 1);
            Bf[ks][nf][0] = packbf(p[0], p[1]);
            Bf[ks][nf][1] = packbf(p[8], p[9]);
        }
    }
    const int dim = tid & 31, brow = tid >> 5;
    float bias_r[4];
#pragma unroll
    for (int G = 0; G < 4; G++)
        bias_r[G] = g_bias[dir * 2048 + G * 512 + g * 32 + dim];
    float cs0 = 0.f, cs1 = 0.f;

    const unsigned lmA  = (unsigned)((l & 15) * WP + (l >> 4) * 16);
    const unsigned lmB  = (unsigned)(((l & 7) + ((l >> 4) << 3)) * WP + ((l >> 3) & 1) * 16);
    const unsigned lmAb = (unsigned)((l & 15) * 1040 + (l >> 4) * 16);
    const unsigned ws_w = smb + WS_OFF + (unsigned)(w * 16) * WP;

    // issue x-tile cp.async for step 0
    {
        const int t0 = dir ? (TT - 1) : 0;
        for (int i = tid; i < 1088; i += 256) {
            int row = i / 68, col = i % 68;
            unsigned dst = smb + XS_OFF + row * WP + col * 16;
            const char* src = (const char*)g_xb
                + ((size_t)(t0 * 32 + bh * 16 + row)) * (LDK * 2) + col * 16;
            asm volatile("cp.async.cg.shared.global [%0],[%1],16;" :: "r"(dst), "l"(src));
        }
        asm volatile("cp.async.commit_group;");
    }

    for (int step = 0; step < TT; step++) {
        const int t = dir ? (TT - 1 - step) : step;
        asm volatile("cp.async.wait_group 0;");
        __syncthreads();   // Xs ready; prior hloc/Ab reads done

        float acc[2][4] = {{0.f,0.f,0.f,0.f},{0.f,0.f,0.f,0.f}};
        // ---- x projection (overlaps peers still finishing prior step) ----
#pragma unroll 4
        for (int ks = 0; ks < 34; ks++) {
            unsigned a0, a1, a2, a3, b0, b1, b2, b3;
            unsigned aaddr = smb + XS_OFF + (unsigned)(ks * 32) + lmA;
            asm volatile("ldmatrix.sync.aligned.m8n8.x4.shared.b16 {%0,%1,%2,%3},[%4];"
                         : "=r"(a0), "=r"(a1), "=r"(a2), "=r"(a3) : "r"(aaddr));
            unsigned baddr = ws_w + (unsigned)(ks * 32) + lmB;
            asm volatile("ldmatrix.sync.aligned.m8n8.x4.shared.b16 {%0,%1,%2,%3},[%4];"
                         : "=r"(b0), "=r"(b1), "=r"(b2), "=r"(b3) : "r"(baddr));
            mma_bf16(acc[0][0], acc[0][1], acc[0][2], acc[0][3], a0, a1, a2, a3, b0, b1);
            mma_bf16(acc[1][0], acc[1][1], acc[1][2], acc[1][3], a0, a1, a2, a3, b2, b3);
        }
        // ---- recurrent part: h of previous step already in Ab ----
        if (step > 0) {
            asm volatile("barrier.cluster.wait.aligned;" ::: "memory");  // acquire
            const unsigned abb = smb + AB_OFF + (unsigned)(((step - 1) & 1) * 16640);
#pragma unroll
            for (int ks = 0; ks < 32; ks++) {
                unsigned a0, a1, a2, a3;
                unsigned addr = abb + (unsigned)(ks * 32) + lmAb;
                asm volatile("ldmatrix.sync.aligned.m8n8.x4.shared.b16 {%0,%1,%2,%3},[%4];"
                             : "=r"(a0), "=r"(a1), "=r"(a2), "=r"(a3) : "r"(addr));
#pragma unroll
                for (int nf = 0; nf < 2; nf++)
                    mma_bf16(acc[nf][0], acc[nf][1], acc[nf][2], acc[nf][3],
                             a0, a1, a2, a3, Bf[ks][nf][0], Bf[ks][nf][1]);
            }
        }
        // ---- scatter C: gsm[n=gate-row][m=batch] ----
        {
            const int m0 = l >> 2;
#pragma unroll
            for (int nf = 0; nf < 2; nf++) {
                int n0 = w * 16 + nf * 8 + ((l & 3) << 1);
                gsm[(n0    ) * 17 + m0    ] = acc[nf][0];
                gsm[(n0 + 1) * 17 + m0    ] = acc[nf][1];
                gsm[(n0    ) * 17 + m0 + 8] = acc[nf][2];
                gsm[(n0 + 1) * 17 + m0 + 8] = acc[nf][3];
            }
        }
        __syncthreads();
        // ---- gates + c/h update; h -> hloc staging ----
        __nv_bfloat16* hloc = (__nv_bfloat16*)(sm + HL_OFF);
#pragma unroll
        for (int pi = 0; pi < 2; pi++) {
            int m = brow + pi * 8;
            float gi = gsm[(dim     ) * 17 + m] + bias_r[0];
            float gf = gsm[(32 + dim) * 17 + m] + bias_r[1];
            float gg = gsm[(64 + dim) * 17 + m] + bias_r[2];
            float go = gsm[(96 + dim) * 17 + m] + bias_r[3];
            float si = fsig(gi), sf = fsig(gf), so = fsig(go);
            float& cs = pi ? cs1 : cs0;
            cs = sf * cs + si * ftanh(gg);
            float h = so * ftanh(cs);
            hloc[m * 32 + dim] = __float2bfloat16(h);
        }
        __syncthreads();   // hloc complete (and gsm reads done)
        // ---- DSMEM broadcast: hloc (1KB) -> all 16 peers' Ab buf[step&1] ---
        // SKIPPED on the last step: no arrive follows, peers may exit.
        if (step + 1 < TT) {
            const unsigned bufo = (unsigned)(AB_OFF + (step & 1) * 16640);
            for (int i = tid; i < 1024; i += 256) {
                int peer = i >> 6, idx = i & 63;
                int row = idx >> 2, q = idx & 3;
                uint4 v = *(const uint4*)(sm + HL_OFF + idx * 16);
                unsigned laddr = smb + bufo + (unsigned)(row * 1040 + g * 64 + q * 16);
                asm volatile(
                    "{\n\t.reg .b32 r;\n\t"
                    "mapa.shared::cluster.u32 r, %0, %1;\n\t"
                    "st.shared::cluster.v4.b32 [r], {%2,%3,%4,%5};\n\t}"
                    :: "r"(laddr), "r"(peer), "r"(v.x), "r"(v.y), "r"(v.z), "r"(v.w)
                    : "memory");
            }
            asm volatile("barrier.cluster.arrive.aligned;" ::: "memory");  // release
        }
        // ---- prefetch next step's x tile (right after arrive) ----
        if (step + 1 < TT) {
            const int tn = dir ? (TT - 2 - step) : (step + 1);
            for (int i = tid; i < 1088; i += 256) {
                int row = i / 68, col = i % 68;
                unsigned dst = smb + XS_OFF + row * WP + col * 16;
                const char* src = (const char*)g_xb
                    + ((size_t)(tn * 32 + bh * 16 + row)) * (LDK * 2) + col * 16;
                asm volatile("cp.async.cg.shared.global [%0],[%1],16;" :: "r"(dst), "l"(src));
            }
            asm volatile("cp.async.commit_group;");
        }
        // ---- global copy for ln_emit (fully off the release path) ----
        if (tid < 64) {
            int row = tid >> 2, q = tid & 3;
            uint4 v = *(const uint4*)(sm + HL_OFF + tid * 16);
            *(uint4*)((char*)g_hs
                + ((((size_t)dir * TT + t) * 2 + bh) * 8192 + g * 512 + row * 32) * 2
                + q * 16) = v;
        }
    }
}

// ---- K4: LayerNorm(1024) + ReLU + emission; h layout [dir][t][bh][g][b][32]
__global__ void __launch_bounds__(256) ln_emit_k(const float* __restrict__ lng,
                                                 const float* __restrict__ lnb,
                                                 const float* __restrict__ wout,
                                                 const float* __restrict__ bout) {
    __shared__ float sh[1024];
    __shared__ float rs[8], rs2[8];
    __shared__ float s_mu, s_rstd;
    const int row = blockIdx.x, tid = threadIdx.x;
    const int lane = tid & 31, w = tid >> 5;
    const int t = row >> 5, b = row & 31;
    const int bh = b >> 4, bl = b & 15;
    const __nv_bfloat16* hf = g_hs + ((size_t)t * 2 + bh) * 8192 + bl * 32;
    const __nv_bfloat16* hb = hf + (size_t)TT * 2 * 8192;
    float s = 0.f, s2 = 0.f;
#pragma unroll
    for (int i = 0; i < 4; i++) {
        int idx = tid + i * 256;
        int d = idx & 511;
        int gg = d >> 5, dm = d & 31;
        float x = (idx < 512) ? __bfloat162float(hf[gg * 512 + dm])
                              : __bfloat162float(hb[gg * 512 + dm]);
        sh[idx] = x; s += x; s2 += x * x;
    }
    for (int o = 16; o; o >>= 1) {
        s  += __shfl_down_sync(0xffffffffu, s, o);
        s2 += __shfl_down_sync(0xffffffffu, s2, o);
    }
    if (!lane) { rs[w] = s; rs2[w] = s2; }
    __syncthreads();
    if (!tid) {
        float S = 0.f, S2 = 0.f;
        for (int i = 0; i < 8; i++) { S += rs[i]; S2 += rs2[i]; }
        float mu = S * (1.f / 1024.f);
        s_mu = mu;
        s_rstd = rsqrtf(S2 * (1.f / 1024.f) - mu * mu + 1e-5f);
    }
    __syncthreads();
    float mu = s_mu, rstd = s_rstd;
#pragma unroll
    for (int i = 0; i < 4; i++) {
        int idx = tid + i * 256;
        float x = (sh[idx] - mu) * rstd * lng[idx] + lnb[idx];
        sh[idx] = fmaxf(x, 0.f);
    }
    __syncthreads();
    if (w < 6) {
        float acc = 0.f;
        for (int i = lane; i < 1024; i += 32) acc = fmaf(sh[i], wout[w * 1024 + i], acc);
        for (int o = 16; o; o >>= 1) acc += __shfl_down_sync(0xffffffffu, acc, o);
        if (!lane) g_em[(size_t)row * 6 + w] = acc + bout[w];
    }
}

// ---- K5: CRF. mask is int32. -----------------------------------------------
__global__ void crf_k(const int* __restrict__ tags, const int* __restrict__ mask,
                      const float* __restrict__ st, const float* __restrict__ en,
                      const float* __restrict__ tr, float* __restrict__ out) {
    __shared__ float ll[32];
    const unsigned full = 0xffffffffu;
    const int b = threadIdx.x >> 5, j = threadIdx.x & 31;
    const bool act = j < 6;
    float trc[6];
#pragma unroll
    for (int i = 0; i < 6; i++) trc[i] = tr[i * 6 + (act ? j : 0)];
    float alpha = act ? (st[j] + g_em[b * 6 + j]) : -1e30f;
    int prev = tags[b * TT];
    float score = st[prev] + g_em[b * 6 + prev];
    int cnt = (mask[b * TT] != 0) ? 1 : 0;
    for (int t = 1; t < TT; t++) {
        float m = (mask[b * TT + t] != 0) ? 1.f : 0.f;
        cnt += (int)m;
        int tg = tags[b * TT + t];
        const float* emt = g_em + ((size_t)t * BB + b) * 6;
        score += m * (tr[prev * 6 + tg] + emt[tg]);
        prev = tg;
        float av[6];
#pragma unroll
        for (int i = 0; i < 6; i++) av[i] = __shfl_sync(full, alpha, i);
        if (act) {
            float mx = -1e30f;
#pragma unroll
            for (int i = 0; i < 6; i++) mx = fmaxf(mx, av[i] + trc[i]);
            float sm = 0.f;
#pragma unroll
            for (int i = 0; i < 6; i++) sm += __expf(av[i] + trc[i] - mx);
            float nxt = mx + __logf(sm) + emt[j];
            if (m > 0.f) alpha = nxt;
        }
    }
    int ltag = tags[b * TT + (cnt - 1)];
    float num = score + en[ltag];
    float v = act ? (alpha + en[j]) : -1e30f;
    float mx = v;
    for (int o = 16; o; o >>= 1) mx = fmaxf(mx, __shfl_xor_sync(full, mx, o));
    float sm = act ? __expf(v - mx) : 0.f;
    for (int o = 16; o; o >>= 1) sm += __shfl_xor_sync(full, sm, o);
    float den = mx + __logf(sm);
    if (j == 0) ll[b] = num - den;
    __syncthreads();
    if (threadIdx.x == 0) {
        float s = 0.f;
        for (int i = 0; i < 32; i++) s += ll[i];
        *out = -s * (1.f / 32.f);
    }
}

extern "C" void kernel_launch(void* const* d_in, const int* in_sizes, int n_in,
                              void* d_out, int out_size) {
    const int*   ids  = (const int*)  d_in[0];
    const float* eeg  = (const float*)d_in[1];
    const int*   tags = (const int*)  d_in[2];
    const int*   mask = (const int*)  d_in[3];
    const float* emb  = (const float*)d_in[4];
    const float* wihf = (const float*)d_in[5];
    const float* whhf = (const float*)d_in[6];
    const float* bf   = (const float*)d_in[7];
    const float* wihb = (const float*)d_in[8];
    const float* whhb = (const float*)d_in[9];
    const float* bb   = (const float*)d_in[10];
    const float* lng  = (const float*)d_in[11];
    const float* lnb  = (const float*)d_in[12];
    const float* wout = (const float*)d_in[13];
    const float* bout = (const float*)d_in[14];
    const float* st   = (const float*)d_in[15];
    const float* en   = (const float*)d_in[16];
    const float* tr   = (const float*)d_in[17];
    float* out = (float*)d_out;

    cudaFuncSetAttribute(lstm_fused_k, cudaFuncAttributeMaxDynamicSharedMemorySize, LSTM_SMEM);
    cudaFuncSetAttribute(lstm_fused_k, cudaFuncAttributeNonPortableClusterSizeAllowed, 1);

    build_x_k<<<NROWS, 128>>>(ids, eeg, emb);
    pack_w_k<<<NG, 128>>>(wihf, wihb, bf, bb);

    cudaLaunchConfig_t cfg = {};
    cfg.gridDim = dim3(64, 1, 1);
    cfg.blockDim = dim3(256, 1, 1);
    cfg.dynamicSmemBytes = LSTM_SMEM;
    cfg.stream = 0;
    cudaLaunchAttribute attrs[1];
    attrs[0].id = cudaLaunchAttributeClusterDimension;
    attrs[0].val.clusterDim.x = 16;
    attrs[0].val.clusterDim.y = 1;
    attrs[0].val.clusterDim.z = 1;
    cfg.attrs = attrs;
    cfg.numAttrs = 1;
    cudaLaunchKernelEx(&cfg, lstm_fused_k, whhf, whhb);

    ln_emit_k<<<NROWS, 256>>>(lng, lnb, wout, bout);
    crf_k<<<1, 1024>>>(tags, mask, st, en, tr, out);
}